// round 7
// baseline (speedup 1.0000x reference)
#include <cuda_runtime.h>
#include <math.h>

#define TT 50
#define NB 2048
#define NS 32
#define NC 16
#define NN 48
#define LDQ 52
#define LDF 52
#define LDV 33
#define LDK 36
#define FULLM 0xffffffffu
#define NTHREADS 256

// smem layout (floats) in one flat array
#define SQ_SZ 2496   // 48*52
#define SF_SZ 1664   // 32*52
#define O_SQ(p)  ((p)*SQ_SZ)
#define O_SF(p)  (4992 + (p)*SF_SZ)
#define O_SW     8320
#define O_SV     9984
#define O_SK     11040
#define O_SCV(p) (11616 + (p)*48)
#define O_SFV(p) (11712 + (p)*32)
#define O_SQV    11776
#define O_SVV    11824
#define O_SKV    11856
#define O_SX     11872
#define O_SX2    11920
#define O_SL     11952   // 16*17: sL[j*17+i] = L[i][j] (col per lane j)
#define O_SDI    12224   // 16 inverse diagonals
#define SMEM_TOT 12240   // 48960 B
// forward-pass aliases (sW/sV dead in forward)
#define O_K2(p)  (O_SW + (p)*576)
#define O_KV2(p) (O_SV + (p)*16)

__device__ float g_K[(size_t)TT * NB * NC * NS];
__device__ float g_k[(size_t)TT * NB * NC];

#define BARSYNC(id, cnt)   asm volatile("bar.sync %0, %1;"   :: "r"(id), "r"(cnt) : "memory")
#define BARARRIVE(id, cnt) asm volatile("bar.arrive %0, %1;" :: "r"(id), "r"(cnt) : "memory")

__device__ __forceinline__ void cp16(float* smem_dst, const float* gmem_src) {
    unsigned sa = (unsigned)__cvta_generic_to_shared(smem_dst);
    asm volatile("cp.async.cg.shared.global [%0], [%1], 16;" :: "r"(sa), "l"(gmem_src));
}
#define CP_COMMIT() asm volatile("cp.async.commit_group;")
#define CP_WAIT(n)  asm volatile("cp.async.wait_group %0;" :: "n"(n))

// triangular solves via registers+shuffles (proven fast path); static indices
__device__ __forceinline__ void trisolve(float* y, const float* a, const float* di)
{
    #pragma unroll
    for (int k = 0; k < 16; ++k) {
        y[k] *= di[k];
        #pragma unroll
        for (int i = k + 1; i < 16; ++i)
            y[i] -= __shfl_sync(FULLM, a[i], k) * y[k];
    }
    #pragma unroll
    for (int k = 15; k >= 0; --k) {
        y[k] *= di[k];
        #pragma unroll
        for (int i = 0; i < k; ++i)
            y[i] -= __shfl_sync(FULLM, a[k], i) * y[k];
    }
}

// In-register Cholesky of Quu on warp 0 (lane j owns column j)
__device__ __forceinline__ void chol16(int lane, const float* sQp, float* a, float* di)
{
    if (lane < 16) {
        #pragma unroll
        for (int i = 0; i < 16; ++i)
            a[i] = sQp[(NS + i) * LDQ + NS + lane];
    }
    #pragma unroll
    for (int k = 0; k < 16; ++k) {
        float akk = __shfl_sync(FULLM, a[k], k);
        float dinv = rsqrtf(akk);
        di[k] = dinv;
        if (lane == k) {
            #pragma unroll
            for (int i = 0; i < 16; ++i)
                if (i >= k) a[i] *= dinv;
        }
        float l[16];
        float ljk = 0.0f;
        #pragma unroll
        for (int i = k + 1; i < 16; ++i) {
            l[i] = __shfl_sync(FULLM, a[i], k);
            if (lane == i) ljk = l[i];
        }
        if (lane > k && lane < 16) {
            #pragma unroll
            for (int i = k + 1; i < 16; ++i)
                if (i >= lane) a[i] -= l[i] * ljk;
        }
    }
}

// Terminal-step factor: warp 0 does everything (once per kernel).
__device__ __forceinline__ void factor_w0_full(int lane, const float* sQp, const float* qu,
                                               float* sK, float* skv)
{
    float a[16], di[16];
    chol16(lane, sQp, a, di);
    float y[16];
    #pragma unroll
    for (int u = 0; u < 16; ++u) y[u] = sQp[(NS + u) * LDQ + lane];
    trisolve(y, a, di);
    #pragma unroll
    for (int u = 0; u < 16; ++u) sK[u * LDK + lane] = -y[u];
    #pragma unroll
    for (int u = 0; u < 16; ++u) y[u] = qu[u];
    trisolve(y, a, di);
    #pragma unroll
    for (int u = 0; u < 16; ++u)
        if (lane == u) skv[u] = -y[u];   // static register indices only
}

// p3: V = Qxx + Qxu@K -> sV ; v = qx + Qxu k ; spill K,k to global.
__device__ __forceinline__ void p3_phase(float* sm, int tid, int t, int b,
                                         const float* sQp, const float* qx)
{
    const float* sK = sm + O_SK;
    float* sV = sm + O_SV;
    int i = tid & 31, g = tid >> 5, j0 = 4 * g;
    float4 acc = *(const float4*)&sQp[i * LDQ + j0];
    #pragma unroll
    for (int u = 0; u < 16; ++u) {
        float q = sQp[(NS + u) * LDQ + i];
        float4 k4 = *(const float4*)&sK[u * LDK + j0];
        acc.x += q * k4.x; acc.y += q * k4.y; acc.z += q * k4.z; acc.w += q * k4.w;
    }
    sV[i * LDV + j0 + 0] = acc.x;
    sV[i * LDV + j0 + 1] = acc.y;
    sV[i * LDV + j0 + 2] = acc.z;
    sV[i * LDV + j0 + 3] = acc.w;
    if (tid < NS) {
        const float* skv = sm + O_SKV;
        float a = qx[i];
        #pragma unroll
        for (int u = 0; u < 16; ++u) a += sQp[(NS + u) * LDQ + i] * skv[u];
        sm[O_SVV + i] = a;
    }
    float* gK = g_K + ((size_t)t * NB + b) * (NC * NS);
    #pragma unroll
    for (int m = 0; m < 2; ++m) {
        int idx = m * NTHREADS + tid;
        gK[idx] = sK[(idx >> 5) * LDK + (idx & 31)];
    }
    if (tid < NC)
        g_k[((size_t)t * NB + b) * NC + tid] = sm[O_SKV + tid];
}

__device__ __forceinline__ void issue_bwd(float* sm, int tid, int t, int b,
                                          const float* Cin, const float* cin,
                                          const float* Fin, const float* fin,
                                          int buf, bool withF)
{
    {
        const float* src = Cin + ((size_t)t * NB + b) * (NN * NN);
        float* dst = sm + O_SQ(buf);
        #pragma unroll
        for (int m = 0; m < 3; ++m) {
            int idx = m * NTHREADS + tid;
            if (idx < 576) {
                int row = idx / 12, c4 = idx % 12;
                cp16(dst + row * LDQ + c4 * 4, src + idx * 4);
            }
        }
    }
    if (tid < 12)
        cp16(sm + O_SCV(buf) + tid * 4, cin + ((size_t)t * NB + b) * NN + tid * 4);
    if (withF) {
        const float* src = Fin + ((size_t)t * NB + b) * (NS * NN);
        float* dst = sm + O_SF(buf);
        #pragma unroll
        for (int m = 0; m < 2; ++m) {
            int idx = m * NTHREADS + tid;
            if (idx < 384) {
                int row = idx / 12, c4 = idx % 12;
                cp16(dst + row * LDF + c4 * 4, src + idx * 4);
            }
        }
        if (tid < 8)
            cp16(sm + O_SFV(buf) + tid * 4, fin + ((size_t)t * NB + b) * NS + tid * 4);
    }
}

__device__ __forceinline__ void issue_fwd(float* sm, int tid, int t, int b,
                                          const float* Fin, const float* fin,
                                          int buf, bool withF)
{
    if (tid < 128) {
        const float* srcK = g_K + ((size_t)t * NB + b) * (NC * NS);
        int row = tid >> 3, c = tid & 7;
        cp16(sm + O_K2(buf) + row * LDK + c * 4, srcK + tid * 4);
    }
    if (tid < 4)
        cp16(sm + O_KV2(buf) + tid * 4, g_k + ((size_t)t * NB + b) * NC + tid * 4);
    if (withF) {
        const float* src = Fin + ((size_t)t * NB + b) * (NS * NN);
        float* dst = sm + O_SF(buf);
        #pragma unroll
        for (int m = 0; m < 2; ++m) {
            int idx = m * NTHREADS + tid;
            if (idx < 384) {
                int row = idx / 12, c4 = idx % 12;
                cp16(dst + row * LDF + c4 * 4, src + idx * 4);
            }
        }
        if (tid < 8)
            cp16(sm + O_SFV(buf) + tid * 4, fin + ((size_t)t * NB + b) * NS + tid * 4);
    }
}

__global__ __launch_bounds__(NTHREADS, 4)
void lqr_kernel(const float* __restrict__ x0,
                const float* __restrict__ Cin,
                const float* __restrict__ cin,
                const float* __restrict__ Fin,
                const float* __restrict__ fin,
                float* __restrict__ out)
{
    const int b = blockIdx.x;
    const int tid = threadIdx.x;
    const int lane = tid & 31;
    const int warp = tid >> 5;

    __shared__ __align__(16) float sm[SMEM_TOT];

    // =============================== BACKWARD ===============================
    issue_bwd(sm, tid, TT - 1, b, Cin, cin, Fin, fin, 1, false);
    CP_COMMIT();
    issue_bwd(sm, tid, TT - 2, b, Cin, cin, Fin, fin, 0, true);
    CP_COMMIT();
    CP_WAIT(1);
    __syncthreads();

    if (warp == 0)
        factor_w0_full(lane, sm + O_SQ(1), sm + O_SCV(1) + NS, sm + O_SK, sm + O_SKV);
    __syncthreads();
    p3_phase(sm, tid, TT - 1, b, sm + O_SQ(1), sm + O_SCV(1));
    __syncthreads();

    for (int t = TT - 2; t >= 0; --t) {
        const int p = t & 1;
        if (t > 0) {
            issue_bwd(sm, tid, t - 1, b, Cin, cin, Fin, fin, 1 - p, true);
            CP_COMMIT();
            CP_WAIT(1);
        } else {
            CP_WAIT(0);
        }
        __syncthreads(); // B0

        float* sQp = sm + O_SQ(p);
        const float* Fp = sm + O_SF(p);
        const float* sV = sm + O_SV;
        float* sW = sm + O_SW;

        // ---- P1: W = V @ F (V symmetric) ----
        {
            int i = lane, j0 = 6 * warp;
            float2 a0 = {0.f, 0.f}, a1 = a0, a2 = a0;
            #pragma unroll 8
            for (int s = 0; s < NS; ++s) {
                float v = sV[i * LDV + s];
                float2 f0 = *(const float2*)&Fp[s * LDF + j0];
                float2 f1 = *(const float2*)&Fp[s * LDF + j0 + 2];
                float2 f2 = *(const float2*)&Fp[s * LDF + j0 + 4];
                a0.x += v * f0.x; a0.y += v * f0.y;
                a1.x += v * f1.x; a1.y += v * f1.y;
                a2.x += v * f2.x; a2.y += v * f2.y;
            }
            *(float2*)&sW[i * LDF + j0]     = a0;
            *(float2*)&sW[i * LDF + j0 + 2] = a1;
            *(float2*)&sW[i * LDF + j0 + 4] = a2;
        }
        __syncthreads(); // B1

        // ---- P2 + factor, overlapped with named barriers ----
        if (tid < 64) {
            // Quu: rows 32..47 cols 32..47; 4 cols per thread
            int row = NS + (tid >> 2), col0 = NS + (tid & 3) * 4;
            float4 q = *(const float4*)&sQp[row * LDQ + col0];
            #pragma unroll 8
            for (int s = 0; s < NS; ++s) {
                float4 w = *(const float4*)&sW[s * LDF + col0];
                float fv = Fp[s * LDF + row];
                q.x += fv * w.x; q.y += fv * w.y; q.z += fv * w.z; q.w += fv * w.w;
            }
            *(float4*)&sQp[row * LDQ + col0] = q;
            BARSYNC(1, 64);  // Quu complete
            if (warp == 0) {
                // Cholesky; export L/di; wait Qux; K-solve
                float a[16], di[16];
                chol16(lane, sQp, a, di);
                if (lane < 16) {
                    #pragma unroll
                    for (int i2 = 0; i2 < 16; ++i2)
                        sm[O_SL + lane * 17 + i2] = a[i2];
                }
                if (lane == 0) {
                    #pragma unroll
                    for (int k = 0; k < 16; ++k) sm[O_SDI + k] = di[k];
                }
                BARARRIVE(3, 128);   // L/di published (for warp 1)
                BARSYNC(2, 96);      // wait for Qux (warps 2,3)
                float y[16];
                #pragma unroll
                for (int u = 0; u < 16; ++u) y[u] = sQp[(NS + u) * LDQ + lane];
                trisolve(y, a, di);
                float* sK = sm + O_SK;
                #pragma unroll
                for (int u = 0; u < 16; ++u) sK[u * LDK + lane] = -y[u];
            } else {
                // warp 1: z-solve, concurrent with warp 0's K-solve
                BARSYNC(3, 128);     // L/di + qu ready
                float a[16], di[16], z[16];
                if (lane < 16) {
                    #pragma unroll
                    for (int i2 = 0; i2 < 16; ++i2)
                        a[i2] = sm[O_SL + lane * 17 + i2];
                }
                #pragma unroll
                for (int i2 = 0; i2 < 16; ++i2) di[i2] = sm[O_SDI + i2];
                #pragma unroll
                for (int u = 0; u < 16; ++u) z[u] = sm[O_SQV + NS + u];
                trisolve(z, a, di);
                #pragma unroll
                for (int u = 0; u < 16; ++u)
                    if (lane == u) sm[O_SKV + u] = -z[u];
            }
        } else if (tid < 128) {
            // warps 2,3: Qux rows 32..47 cols 0..31 (8 cols/thread), then qv
            int t2 = tid - 64;
            int row = NS + (t2 >> 2), col0 = (t2 & 3) * 8;
            float4 qa = *(const float4*)&sQp[row * LDQ + col0];
            float4 qb = *(const float4*)&sQp[row * LDQ + col0 + 4];
            #pragma unroll 8
            for (int s = 0; s < NS; ++s) {
                float4 wa = *(const float4*)&sW[s * LDF + col0];
                float4 wb = *(const float4*)&sW[s * LDF + col0 + 4];
                float fv = Fp[s * LDF + row];
                qa.x += fv * wa.x; qa.y += fv * wa.y; qa.z += fv * wa.z; qa.w += fv * wa.w;
                qb.x += fv * wb.x; qb.y += fv * wb.y; qb.z += fv * wb.z; qb.w += fv * wb.w;
            }
            *(float4*)&sQp[row * LDQ + col0] = qa;
            *(float4*)&sQp[row * LDQ + col0 + 4] = qb;
            BARARRIVE(2, 96);   // Qux published (for warp 0's K-solve)
            if (t2 < NN) {
                // qv_j = c_j + F^T v + W^T f
                const float* sv = sm + O_SVV;
                const float* sfv = sm + O_SFV(p);
                float a = sm[O_SCV(p) + t2];
                #pragma unroll 8
                for (int s = 0; s < NS; ++s)
                    a += Fp[s * LDF + t2] * sv[s] + sW[s * LDF + t2] * sfv[s];
                sm[O_SQV + t2] = a;
            }
            BARARRIVE(3, 128);  // qu published (for warp 1's z-solve)
        } else {
            // warps 4-7: Qxx rows 0..31 cols 0..47 (12 cols/thread)
            int t3 = tid - 128;
            int row = t3 >> 2, col0 = (t3 & 3) * 12;
            float4 qa = *(const float4*)&sQp[row * LDQ + col0];
            float4 qb = *(const float4*)&sQp[row * LDQ + col0 + 4];
            float4 qc = *(const float4*)&sQp[row * LDQ + col0 + 8];
            #pragma unroll 8
            for (int s = 0; s < NS; ++s) {
                float4 wa = *(const float4*)&sW[s * LDF + col0];
                float4 wb = *(const float4*)&sW[s * LDF + col0 + 4];
                float4 wc = *(const float4*)&sW[s * LDF + col0 + 8];
                float fv = Fp[s * LDF + row];
                qa.x += fv * wa.x; qa.y += fv * wa.y; qa.z += fv * wa.z; qa.w += fv * wa.w;
                qb.x += fv * wb.x; qb.y += fv * wb.y; qb.z += fv * wb.z; qb.w += fv * wb.w;
                qc.x += fv * wc.x; qc.y += fv * wc.y; qc.z += fv * wc.z; qc.w += fv * wc.w;
            }
            *(float4*)&sQp[row * LDQ + col0] = qa;
            *(float4*)&sQp[row * LDQ + col0 + 4] = qb;
            *(float4*)&sQp[row * LDQ + col0 + 8] = qc;
        }
        __syncthreads(); // B3: K, skv, Qxx, qv all ready

        p3_phase(sm, tid, t, b, sQp, sm + O_SQV);
        __syncthreads(); // B4
    }

    // =============================== FORWARD ================================
    if (tid < NS) sm[O_SX + tid] = x0[(size_t)b * NS + tid];
    issue_fwd(sm, tid, 0, b, Fin, fin, 0, true);
    CP_COMMIT();

    for (int t = 0; t < TT - 1; ++t) {
        const int pf = t & 1;
        issue_fwd(sm, tid, t + 1, b, Fin, fin, 1 - pf, t + 1 < TT - 1);
        CP_COMMIT();
        CP_WAIT(1);
        __syncthreads();

        if (warp == 0) {
            const float* sK2 = sm + O_K2(pf);
            int u = lane & 15, h = lane >> 4;
            float acc = 0.0f;
            #pragma unroll
            for (int ii = 0; ii < 16; ++ii)
                acc += sK2[u * LDK + h * 16 + ii] * sm[O_SX + h * 16 + ii];
            acc += __shfl_xor_sync(FULLM, acc, 16);
            if (lane < 16) sm[O_SX + NS + lane] = acc + sm[O_KV2(pf) + lane];
        }
        __syncthreads();

        if (tid < NN) out[((size_t)t * NB + b) * NN + tid] = sm[O_SX + tid];
        if (tid < NS) {
            const float* Fp = sm + O_SF(pf);
            float a = sm[O_SFV(pf) + tid];
            #pragma unroll 8
            for (int j = 0; j < NN; ++j) a += Fp[tid * LDF + j] * sm[O_SX + j];
            sm[O_SX2 + tid] = a;
        }
        __syncthreads();
        if (tid < NS) sm[O_SX + tid] = sm[O_SX2 + tid];
    }

    // final step t = TT-1 (buffer parity 1)
    CP_WAIT(0);
    __syncthreads();
    if (warp == 0) {
        const float* sK2 = sm + O_K2(1);
        int u = lane & 15, h = lane >> 4;
        float acc = 0.0f;
        #pragma unroll
        for (int ii = 0; ii < 16; ++ii)
            acc += sK2[u * LDK + h * 16 + ii] * sm[O_SX + h * 16 + ii];
        acc += __shfl_xor_sync(FULLM, acc, 16);
        if (lane < 16) sm[O_SX + NS + lane] = acc + sm[O_KV2(1) + lane];
    }
    __syncthreads();
    if (tid < NN) out[((size_t)(TT - 1) * NB + b) * NN + tid] = sm[O_SX + tid];
}

extern "C" void kernel_launch(void* const* d_in, const int* in_sizes, int n_in,
                              void* d_out, int out_size) {
    const float *x0 = nullptr, *C = nullptr, *c = nullptr, *F = nullptr, *f = nullptr;
    for (int i = 0; i < n_in; ++i) {
        long long s = in_sizes[i];
        if (s == (long long)TT * NB * NN * NN) C = (const float*)d_in[i];
        else if (s == (long long)TT * NB * NN) c = (const float*)d_in[i];
        else if (s == (long long)(TT - 1) * NB * NS * NN) F = (const float*)d_in[i];
        else if (s == (long long)(TT - 1) * NB * NS) f = (const float*)d_in[i];
        else if (s == (long long)NB * NS) x0 = (const float*)d_in[i];
    }
    float* out = (float*)d_out;
    lqr_kernel<<<NB, NTHREADS>>>(x0, C, c, F, f, out);
}

// round 8
// speedup vs baseline: 1.1967x; 1.1967x over previous
#include <cuda_runtime.h>
#include <math.h>

#define TT 50
#define NB 2048
#define NS 32
#define NC 16
#define NN 48
#define LDQ 52
#define LDF 52
#define LDV 33
#define LDK 36
#define FULLM 0xffffffffu
#define NTHREADS 256

// smem layout (floats) in one flat array
#define SQ_SZ 2496   // 48*52
#define SF_SZ 1664   // 32*52
#define O_SQ(p)  ((p)*SQ_SZ)
#define O_SF(p)  (4992 + (p)*SF_SZ)
#define O_SW     8320
#define O_SV     9984
#define O_SK     11040
#define O_SCV(p) (11616 + (p)*48)
#define O_SFV(p) (11712 + (p)*32)
#define O_SQV    11776
#define O_SVV    11824
#define O_SKV    11856
#define O_SX     11872
#define O_SX2    11920
#define SMEM_TOT 11952
// forward-pass aliases (sW/sV regions are dead in forward)
#define O_K2(p)  (O_SW + (p)*576)
#define O_KV2(p) (O_SV + (p)*16)

__device__ float g_K[(size_t)TT * NB * NC * NS];
__device__ float g_k[(size_t)TT * NB * NC];

__device__ __forceinline__ void cp16(float* smem_dst, const float* gmem_src) {
    unsigned sa = (unsigned)__cvta_generic_to_shared(smem_dst);
    asm volatile("cp.async.cg.shared.global [%0], [%1], 16;" :: "r"(sa), "l"(gmem_src));
}
#define CP_COMMIT() asm volatile("cp.async.commit_group;")
#define CP_WAIT(n)  asm volatile("cp.async.wait_group %0;" :: "n"(n))

// Map lower-triangle float4-position p (0..311) -> (row i, col-group g).
// Block-row r (4 rows, r+1 groups); positions before r: 2r(r+1).
__device__ __forceinline__ void p2map(int p, int& i, int& g) {
    int r = (int)((sqrtf((float)(8 * p + 4)) - 2.0f) * 0.25f);
    while (2 * (r + 1) * (r + 2) <= p) ++r;
    while (2 * r * (r + 1) > p) --r;
    int rem = p - 2 * r * (r + 1);
    int k = rem / (r + 1);
    g = rem - k * (r + 1);
    i = 4 * r + k;
}

// triangular solves L y' = y ; L^T y'' = y'  (L in lanes 0..15 of a[], di = 1/diag)
__device__ __forceinline__ void trisolve(float* y, const float* a, const float* di)
{
    #pragma unroll
    for (int k = 0; k < 16; ++k) {
        y[k] *= di[k];
        #pragma unroll
        for (int i = k + 1; i < 16; ++i)
            y[i] -= __shfl_sync(FULLM, a[i], k) * y[k];
    }
    #pragma unroll
    for (int k = 15; k >= 0; --k) {
        y[k] *= di[k];
        #pragma unroll
        for (int i = 0; i < k; ++i)
            y[i] -= __shfl_sync(FULLM, a[k], i) * y[k];
    }
}

// Warp-0 factor. Only the lower triangle of Quu is read (chol uses i>=lane,
// trisolve shuffles only L entries). Final z-store uses static register
// indices (prevents local-memory demotion of y[]).
__device__ __forceinline__ void factor_w0(int lane, const float* sQp, const float* qu,
                                          float* sK, float* skv)
{
    float a[16], di[16];
    if (lane < 16) {
        #pragma unroll
        for (int i = 0; i < 16; ++i)
            a[i] = sQp[(NS + i) * LDQ + NS + lane];
    }
    #pragma unroll
    for (int k = 0; k < 16; ++k) {
        float akk = __shfl_sync(FULLM, a[k], k);
        float dinv = rsqrtf(akk);
        di[k] = dinv;
        if (lane == k) {
            #pragma unroll
            for (int i = 0; i < 16; ++i)
                if (i >= k) a[i] *= dinv;
        }
        float l[16];
        float ljk = 0.0f;
        #pragma unroll
        for (int i = k + 1; i < 16; ++i) {
            l[i] = __shfl_sync(FULLM, a[i], k);
            if (lane == i) ljk = l[i];
        }
        if (lane > k && lane < 16) {
            #pragma unroll
            for (int i = k + 1; i < 16; ++i)
                if (i >= lane) a[i] -= l[i] * ljk;
        }
    }
    // K columns: lane j solves Qux column j (lower block — always computed)
    float y[16];
    #pragma unroll
    for (int u = 0; u < 16; ++u) y[u] = sQp[(NS + u) * LDQ + lane];
    trisolve(y, a, di);
    #pragma unroll
    for (int u = 0; u < 16; ++u) sK[u * LDK + lane] = -y[u];
    // k vector (redundant per lane); static-index predicated store
    #pragma unroll
    for (int u = 0; u < 16; ++u) y[u] = qu[u];
    trisolve(y, a, di);
    #pragma unroll
    for (int u = 0; u < 16; ++u)
        if (lane == u) skv[u] = -y[u];
}

// p3: V = Qxx + Qxu@K -> sV ; v = qx + Qxu k ; spill K,k.
// Qxx init reads are index-swapped into the lower triangle.
__device__ __forceinline__ void p3_phase(float* sm, int tid, int t, int b,
                                         const float* sQp, const float* qx)
{
    const float* sK = sm + O_SK;
    float* sV = sm + O_SV;
    int i = tid & 31, g = tid >> 5, j0 = 4 * g;
    float4 acc;
    {
        int j;
        j = j0 + 0; acc.x = (i >= j) ? sQp[i * LDQ + j] : sQp[j * LDQ + i];
        j = j0 + 1; acc.y = (i >= j) ? sQp[i * LDQ + j] : sQp[j * LDQ + i];
        j = j0 + 2; acc.z = (i >= j) ? sQp[i * LDQ + j] : sQp[j * LDQ + i];
        j = j0 + 3; acc.w = (i >= j) ? sQp[i * LDQ + j] : sQp[j * LDQ + i];
    }
    #pragma unroll
    for (int u = 0; u < 16; ++u) {
        float q = sQp[(NS + u) * LDQ + i];
        float4 k4 = *(const float4*)&sK[u * LDK + j0];
        acc.x += q * k4.x; acc.y += q * k4.y; acc.z += q * k4.z; acc.w += q * k4.w;
    }
    sV[i * LDV + j0 + 0] = acc.x;
    sV[i * LDV + j0 + 1] = acc.y;
    sV[i * LDV + j0 + 2] = acc.z;
    sV[i * LDV + j0 + 3] = acc.w;
    if (tid < NS) {
        const float* skv = sm + O_SKV;
        float a = qx[i];
        #pragma unroll
        for (int u = 0; u < 16; ++u) a += sQp[(NS + u) * LDQ + i] * skv[u];
        sm[O_SVV + i] = a;
    }
    float* gK = g_K + ((size_t)t * NB + b) * (NC * NS);
    #pragma unroll
    for (int m = 0; m < 2; ++m) {
        int idx = m * NTHREADS + tid;
        gK[idx] = sK[(idx >> 5) * LDK + (idx & 31)];
    }
    if (tid < NC)
        g_k[((size_t)t * NB + b) * NC + tid] = sm[O_SKV + tid];
}

__device__ __forceinline__ void issue_bwd(float* sm, int tid, int t, int b,
                                          const float* Cin, const float* cin,
                                          const float* Fin, const float* fin,
                                          int buf, bool withF)
{
    {
        const float* src = Cin + ((size_t)t * NB + b) * (NN * NN);
        float* dst = sm + O_SQ(buf);
        #pragma unroll
        for (int m = 0; m < 3; ++m) {
            int idx = m * NTHREADS + tid;
            if (idx < 576) {
                int row = idx / 12, c4 = idx % 12;
                cp16(dst + row * LDQ + c4 * 4, src + idx * 4);
            }
        }
    }
    if (tid < 12)
        cp16(sm + O_SCV(buf) + tid * 4, cin + ((size_t)t * NB + b) * NN + tid * 4);
    if (withF) {
        const float* src = Fin + ((size_t)t * NB + b) * (NS * NN);
        float* dst = sm + O_SF(buf);
        #pragma unroll
        for (int m = 0; m < 2; ++m) {
            int idx = m * NTHREADS + tid;
            if (idx < 384) {
                int row = idx / 12, c4 = idx % 12;
                cp16(dst + row * LDF + c4 * 4, src + idx * 4);
            }
        }
        if (tid < 8)
            cp16(sm + O_SFV(buf) + tid * 4, fin + ((size_t)t * NB + b) * NS + tid * 4);
    }
}

__device__ __forceinline__ void issue_fwd(float* sm, int tid, int t, int b,
                                          const float* Fin, const float* fin,
                                          int buf, bool withF)
{
    if (tid < 128) {
        const float* srcK = g_K + ((size_t)t * NB + b) * (NC * NS);
        int row = tid >> 3, c = tid & 7;
        cp16(sm + O_K2(buf) + row * LDK + c * 4, srcK + tid * 4);
    }
    if (tid < 4)
        cp16(sm + O_KV2(buf) + tid * 4, g_k + ((size_t)t * NB + b) * NC + tid * 4);
    if (withF) {
        const float* src = Fin + ((size_t)t * NB + b) * (NS * NN);
        float* dst = sm + O_SF(buf);
        #pragma unroll
        for (int m = 0; m < 2; ++m) {
            int idx = m * NTHREADS + tid;
            if (idx < 384) {
                int row = idx / 12, c4 = idx % 12;
                cp16(dst + row * LDF + c4 * 4, src + idx * 4);
            }
        }
        if (tid < 8)
            cp16(sm + O_SFV(buf) + tid * 4, fin + ((size_t)t * NB + b) * NS + tid * 4);
    }
}

__global__ __launch_bounds__(NTHREADS, 4)
void lqr_kernel(const float* __restrict__ x0,
                const float* __restrict__ Cin,
                const float* __restrict__ cin,
                const float* __restrict__ Fin,
                const float* __restrict__ fin,
                float* __restrict__ out)
{
    const int b = blockIdx.x;
    const int tid = threadIdx.x;
    const int lane = tid & 31;
    const int warp = tid >> 5;

    __shared__ __align__(16) float sm[SMEM_TOT];

    // =============================== BACKWARD ===============================
    issue_bwd(sm, tid, TT - 1, b, Cin, cin, Fin, fin, 1, false);
    CP_COMMIT();
    issue_bwd(sm, tid, TT - 2, b, Cin, cin, Fin, fin, 0, true);
    CP_COMMIT();
    CP_WAIT(1);
    __syncthreads();

    if (warp == 0)
        factor_w0(lane, sm + O_SQ(1), sm + O_SCV(1) + NS, sm + O_SK, sm + O_SKV);
    __syncthreads();
    // NOTE: terminal C is fully loaded (both triangles valid) so swapped reads ok
    p3_phase(sm, tid, TT - 1, b, sm + O_SQ(1), sm + O_SCV(1));
    __syncthreads();

    for (int t = TT - 2; t >= 0; --t) {
        const int p = t & 1;
        if (t > 0) {
            issue_bwd(sm, tid, t - 1, b, Cin, cin, Fin, fin, 1 - p, true);
            CP_COMMIT();
            CP_WAIT(1);
        } else {
            CP_WAIT(0);
        }
        __syncthreads(); // B0

        float* sQp = sm + O_SQ(p);
        const float* Fp = sm + O_SF(p);
        const float* sV = sm + O_SV;
        float* sW = sm + O_SW;

        // ---- P1: W = V @ F (V symmetric) ----
        {
            int i = lane, g = warp, j0 = 6 * g;
            float2 a0 = {0.f, 0.f}, a1 = a0, a2 = a0;
            #pragma unroll 8
            for (int s = 0; s < NS; ++s) {
                float v = sV[i * LDV + s];
                float2 f0 = *(const float2*)&Fp[s * LDF + j0];
                float2 f1 = *(const float2*)&Fp[s * LDF + j0 + 2];
                float2 f2 = *(const float2*)&Fp[s * LDF + j0 + 4];
                a0.x += v * f0.x; a0.y += v * f0.y;
                a1.x += v * f1.x; a1.y += v * f1.y;
                a2.x += v * f2.x; a2.y += v * f2.y;
            }
            *(float2*)&sW[i * LDF + j0]     = a0;
            *(float2*)&sW[i * LDF + j0 + 2] = a1;
            *(float2*)&sW[i * LDF + j0 + 4] = a2;
        }
        __syncthreads(); // B1

        // ---- P2: lower triangle of Qm = C + F^T W (312 float4 blocks) ----
        // tids 0..127: two positions (p, p+128); tids 128..183: one (tid+128);
        // tids 192..239: qv. Upper triangle left stale (never read).
        if (tid < 184) {
            const bool two = (tid < 128);
            int pA = two ? tid : (tid + 128);
            int iA, gA; p2map(pA, iA, gA);
            float4 qa = *(const float4*)&sQp[iA * LDQ + 4 * gA];
            int iB = 0, gB = 0;
            float4 qb = {0.f, 0.f, 0.f, 0.f};
            if (two) {
                p2map(tid + 128, iB, gB);
                qb = *(const float4*)&sQp[iB * LDQ + 4 * gB];
            }
            #pragma unroll 8
            for (int s = 0; s < NS; ++s) {
                float fa = Fp[s * LDF + iA];
                float4 wa = *(const float4*)&sW[s * LDF + 4 * gA];
                qa.x += fa * wa.x; qa.y += fa * wa.y;
                qa.z += fa * wa.z; qa.w += fa * wa.w;
                if (two) {
                    float fb = Fp[s * LDF + iB];
                    float4 wb = *(const float4*)&sW[s * LDF + 4 * gB];
                    qb.x += fb * wb.x; qb.y += fb * wb.y;
                    qb.z += fb * wb.z; qb.w += fb * wb.w;
                }
            }
            *(float4*)&sQp[iA * LDQ + 4 * gA] = qa;
            if (two) *(float4*)&sQp[iB * LDQ + 4 * gB] = qb;
        } else if (tid >= 192) {
            int j = tid - 192;
            if (j < NN) {
                const float* sv = sm + O_SVV;
                const float* sfv = sm + O_SFV(p);
                float a = sm[O_SCV(p) + j];
                #pragma unroll 8
                for (int s = 0; s < NS; ++s)
                    a += Fp[s * LDF + j] * sv[s] + sW[s * LDF + j] * sfv[s];
                sm[O_SQV + j] = a;
            }
        }
        __syncthreads(); // B2

        if (warp == 0)
            factor_w0(lane, sQp, sm + O_SQV + NS, sm + O_SK, sm + O_SKV);
        __syncthreads(); // B3

        p3_phase(sm, tid, t, b, sQp, sm + O_SQV);
        __syncthreads(); // B4
    }

    // =============================== FORWARD ================================
    if (tid < NS) sm[O_SX + tid] = x0[(size_t)b * NS + tid];
    issue_fwd(sm, tid, 0, b, Fin, fin, 0, true);
    CP_COMMIT();

    for (int t = 0; t < TT - 1; ++t) {
        const int pf = t & 1;
        issue_fwd(sm, tid, t + 1, b, Fin, fin, 1 - pf, t + 1 < TT - 1);
        CP_COMMIT();
        CP_WAIT(1);
        __syncthreads();

        if (warp == 0) {
            const float* sK2 = sm + O_K2(pf);
            int u = lane & 15, h = lane >> 4;
            float acc = 0.0f;
            #pragma unroll
            for (int ii = 0; ii < 16; ++ii)
                acc += sK2[u * LDK + h * 16 + ii] * sm[O_SX + h * 16 + ii];
            acc += __shfl_xor_sync(FULLM, acc, 16);
            if (lane < 16) sm[O_SX + NS + lane] = acc + sm[O_KV2(pf) + lane];
        }
        __syncthreads();

        if (tid < NN) out[((size_t)t * NB + b) * NN + tid] = sm[O_SX + tid];
        if (tid < NS) {
            const float* Fp = sm + O_SF(pf);
            float a = sm[O_SFV(pf) + tid];
            #pragma unroll 8
            for (int j = 0; j < NN; ++j) a += Fp[tid * LDF + j] * sm[O_SX + j];
            sm[O_SX2 + tid] = a;
        }
        __syncthreads();
        if (tid < NS) sm[O_SX + tid] = sm[O_SX2 + tid];
    }

    // final step t = TT-1 (buffer parity 1)
    CP_WAIT(0);
    __syncthreads();
    if (warp == 0) {
        const float* sK2 = sm + O_K2(1);
        int u = lane & 15, h = lane >> 4;
        float acc = 0.0f;
        #pragma unroll
        for (int ii = 0; ii < 16; ++ii)
            acc += sK2[u * LDK + h * 16 + ii] * sm[O_SX + h * 16 + ii];
        acc += __shfl_xor_sync(FULLM, acc, 16);
        if (lane < 16) sm[O_SX + NS + lane] = acc + sm[O_KV2(1) + lane];
    }
    __syncthreads();
    if (tid < NN) out[((size_t)(TT - 1) * NB + b) * NN + tid] = sm[O_SX + tid];
}

extern "C" void kernel_launch(void* const* d_in, const int* in_sizes, int n_in,
                              void* d_out, int out_size) {
    const float *x0 = nullptr, *C = nullptr, *c = nullptr, *F = nullptr, *f = nullptr;
    for (int i = 0; i < n_in; ++i) {
        long long s = in_sizes[i];
        if (s == (long long)TT * NB * NN * NN) C = (const float*)d_in[i];
        else if (s == (long long)TT * NB * NN) c = (const float*)d_in[i];
        else if (s == (long long)(TT - 1) * NB * NS * NN) F = (const float*)d_in[i];
        else if (s == (long long)(TT - 1) * NB * NS) f = (const float*)d_in[i];
        else if (s == (long long)NB * NS) x0 = (const float*)d_in[i];
    }
    float* out = (float*)d_out;
    lqr_kernel<<<NB, NTHREADS>>>(x0, C, c, F, f, out);
}

// round 10
// speedup vs baseline: 1.3178x; 1.1013x over previous
#include <cuda_runtime.h>
#include <math.h>

#define TT 50
#define NB 2048
#define NS 32
#define NC 16
#define NN 48
#define LDQ 52
#define LDF 52
#define LDV 33
#define LDK 36
#define FULLM 0xffffffffu
#define NTHREADS 256

// smem layout (floats) in one flat array
#define SQ_SZ 2496   // 48*52
#define SF_SZ 1664   // 32*52
#define O_SQ(p)  ((p)*SQ_SZ)
#define O_SF(p)  (4992 + (p)*SF_SZ)
#define O_SW     8320
#define O_SV     9984
#define O_SK     11040
#define O_SCV(p) (11616 + (p)*48)
#define O_SFV(p) (11712 + (p)*32)
#define O_SQV    11776
#define O_SVV    11824
#define O_SKV    11856
#define O_SX     11872
#define O_SX2    11920
#define SMEM_TOT 11952
// forward-pass aliases (sW/sV regions are dead in forward)
#define O_K2(p)  (O_SW + (p)*576)
#define O_KV2(p) (O_SV + (p)*16)

__device__ float g_K[(size_t)TT * NB * NC * NS];
__device__ float g_k[(size_t)TT * NB * NC];

__device__ __forceinline__ void cp16(float* smem_dst, const float* gmem_src) {
    unsigned sa = (unsigned)__cvta_generic_to_shared(smem_dst);
    asm volatile("cp.async.cg.shared.global [%0], [%1], 16;" :: "r"(sa), "l"(gmem_src));
}
#define CP_COMMIT() asm volatile("cp.async.commit_group;")
#define CP_WAIT(n)  asm volatile("cp.async.wait_group %0;" :: "n"(n))

// triangular solves L y' = y ; L^T y'' = y'  (L in lanes 0..15 of a[], di = 1/diag)
__device__ __forceinline__ void trisolve(float* y, const float* a, const float* di)
{
    #pragma unroll
    for (int k = 0; k < 16; ++k) {
        y[k] *= di[k];
        #pragma unroll
        for (int i = k + 1; i < 16; ++i)
            y[i] -= __shfl_sync(FULLM, a[i], k) * y[k];
    }
    #pragma unroll
    for (int k = 15; k >= 0; --k) {
        y[k] *= di[k];
        #pragma unroll
        for (int i = 0; i < k; ++i)
            y[i] -= __shfl_sync(FULLM, a[k], i) * y[k];
    }
}

// Warp-0 factor: Cholesky of Quu (16x16) in registers via shuffles; solve K
// (32 cols lane-parallel), then k (second RHS). The final k-store uses ONLY
// compile-time register indices (predicated per-lane stores) so ptxas never
// demotes y[] to local memory — the single diff vs the round-3 baseline.
__device__ __forceinline__ void factor_w0(int lane, const float* sQp, const float* qu,
                                          float* sK, float* skv)
{
    float a[16], di[16];
    if (lane < 16) {
        #pragma unroll
        for (int i = 0; i < 16; ++i)
            a[i] = sQp[(NS + i) * LDQ + NS + lane];
    }
    #pragma unroll
    for (int k = 0; k < 16; ++k) {
        float akk = __shfl_sync(FULLM, a[k], k);
        float dinv = rsqrtf(akk);
        di[k] = dinv;
        if (lane == k) {
            #pragma unroll
            for (int i = 0; i < 16; ++i)
                if (i >= k) a[i] *= dinv;
        }
        float l[16];
        float ljk = 0.0f;
        #pragma unroll
        for (int i = k + 1; i < 16; ++i) {
            l[i] = __shfl_sync(FULLM, a[i], k);
            if (lane == i) ljk = l[i];
        }
        if (lane > k && lane < 16) {
            #pragma unroll
            for (int i = k + 1; i < 16; ++i)
                if (i >= lane) a[i] -= l[i] * ljk;
        }
    }
    // K columns: lane j solves Qux column j
    float y[16];
    #pragma unroll
    for (int u = 0; u < 16; ++u) y[u] = sQp[(NS + u) * LDQ + lane];
    trisolve(y, a, di);
    #pragma unroll
    for (int u = 0; u < 16; ++u) sK[u * LDK + lane] = -y[u];
    // k vector (redundant across lanes); static-index predicated store
    #pragma unroll
    for (int u = 0; u < 16; ++u) y[u] = qu[u];
    trisolve(y, a, di);
    #pragma unroll
    for (int u = 0; u < 16; ++u)
        if (lane == u) skv[u] = -y[u];
}

// p3: V = Qxx + Qxu@K (written straight to sV, sym skipped — exact in infinite
// precision); v = qx + Qxu k ; spill K,k. Qxu read as Qux rows (== reference).
__device__ __forceinline__ void p3_phase(float* sm, int tid, int t, int b,
                                         const float* sQp, const float* qx)
{
    const float* sK = sm + O_SK;
    float* sV = sm + O_SV;
    int i = tid & 31, g = tid >> 5, j0 = 4 * g;
    float4 acc = *(const float4*)&sQp[i * LDQ + j0];
    #pragma unroll
    for (int u = 0; u < 16; ++u) {
        float q = sQp[(NS + u) * LDQ + i];
        float4 k4 = *(const float4*)&sK[u * LDK + j0];
        acc.x += q * k4.x; acc.y += q * k4.y; acc.z += q * k4.z; acc.w += q * k4.w;
    }
    sV[i * LDV + j0 + 0] = acc.x;
    sV[i * LDV + j0 + 1] = acc.y;
    sV[i * LDV + j0 + 2] = acc.z;
    sV[i * LDV + j0 + 3] = acc.w;
    if (tid < NS) {
        const float* skv = sm + O_SKV;
        float a = qx[i];
        #pragma unroll
        for (int u = 0; u < 16; ++u) a += sQp[(NS + u) * LDQ + i] * skv[u];
        sm[O_SVV + i] = a;
    }
    // spill
    float* gK = g_K + ((size_t)t * NB + b) * (NC * NS);
    #pragma unroll
    for (int m = 0; m < 2; ++m) {
        int idx = m * NTHREADS + tid;
        gK[idx] = sK[(idx >> 5) * LDK + (idx & 31)];
    }
    if (tid < NC)
        g_k[((size_t)t * NB + b) * NC + tid] = sm[O_SKV + tid];
}

// issue cp.async group for backward step t into buffer `buf`
__device__ __forceinline__ void issue_bwd(float* sm, int tid, int t, int b,
                                          const float* Cin, const float* cin,
                                          const float* Fin, const float* fin,
                                          int buf, bool withF)
{
    {
        const float* src = Cin + ((size_t)t * NB + b) * (NN * NN);
        float* dst = sm + O_SQ(buf);
        #pragma unroll
        for (int m = 0; m < 3; ++m) {
            int idx = m * NTHREADS + tid;
            if (idx < 576) {
                int row = idx / 12, c4 = idx % 12;
                cp16(dst + row * LDQ + c4 * 4, src + idx * 4);
            }
        }
    }
    if (tid < 12)
        cp16(sm + O_SCV(buf) + tid * 4, cin + ((size_t)t * NB + b) * NN + tid * 4);
    if (withF) {
        const float* src = Fin + ((size_t)t * NB + b) * (NS * NN);
        float* dst = sm + O_SF(buf);
        #pragma unroll
        for (int m = 0; m < 2; ++m) {
            int idx = m * NTHREADS + tid;
            if (idx < 384) {
                int row = idx / 12, c4 = idx % 12;
                cp16(dst + row * LDF + c4 * 4, src + idx * 4);
            }
        }
        if (tid < 8)
            cp16(sm + O_SFV(buf) + tid * 4, fin + ((size_t)t * NB + b) * NS + tid * 4);
    }
}

// issue cp.async group for forward step t into buffer `buf`
__device__ __forceinline__ void issue_fwd(float* sm, int tid, int t, int b,
                                          const float* Fin, const float* fin,
                                          int buf, bool withF)
{
    if (tid < 128) {
        const float* srcK = g_K + ((size_t)t * NB + b) * (NC * NS);
        int row = tid >> 3, c = tid & 7;
        cp16(sm + O_K2(buf) + row * LDK + c * 4, srcK + tid * 4);
    }
    if (tid < 4)
        cp16(sm + O_KV2(buf) + tid * 4, g_k + ((size_t)t * NB + b) * NC + tid * 4);
    if (withF) {
        const float* src = Fin + ((size_t)t * NB + b) * (NS * NN);
        float* dst = sm + O_SF(buf);
        #pragma unroll
        for (int m = 0; m < 2; ++m) {
            int idx = m * NTHREADS + tid;
            if (idx < 384) {
                int row = idx / 12, c4 = idx % 12;
                cp16(dst + row * LDF + c4 * 4, src + idx * 4);
            }
        }
        if (tid < 8)
            cp16(sm + O_SFV(buf) + tid * 4, fin + ((size_t)t * NB + b) * NS + tid * 4);
    }
}

__global__ __launch_bounds__(NTHREADS, 4)
void lqr_kernel(const float* __restrict__ x0,
                const float* __restrict__ Cin,
                const float* __restrict__ cin,
                const float* __restrict__ Fin,
                const float* __restrict__ fin,
                float* __restrict__ out)
{
    const int b = blockIdx.x;
    const int tid = threadIdx.x;
    const int lane = tid & 31;
    const int warp = tid >> 5;

    __shared__ __align__(16) float sm[SMEM_TOT];

    // =============================== BACKWARD ===============================
    issue_bwd(sm, tid, TT - 1, b, Cin, cin, Fin, fin, 1, false);
    CP_COMMIT();
    issue_bwd(sm, tid, TT - 2, b, Cin, cin, Fin, fin, 0, true);
    CP_COMMIT();
    CP_WAIT(1);
    __syncthreads();

    // terminal factor + p3 (Qm = C49, qv = c49)
    if (warp == 0)
        factor_w0(lane, sm + O_SQ(1), sm + O_SCV(1) + NS, sm + O_SK, sm + O_SKV);
    __syncthreads();
    p3_phase(sm, tid, TT - 1, b, sm + O_SQ(1), sm + O_SCV(1));
    __syncthreads();

    for (int t = TT - 2; t >= 0; --t) {
        const int p = t & 1;
        if (t > 0) {
            issue_bwd(sm, tid, t - 1, b, Cin, cin, Fin, fin, 1 - p, true);
            CP_COMMIT();
            CP_WAIT(1);
        } else {
            CP_WAIT(0);
        }
        __syncthreads(); // B0

        float* sQp = sm + O_SQ(p);
        const float* Fp = sm + O_SF(p);
        const float* sV = sm + O_SV;
        float* sW = sm + O_SW;

        // ---- P1: W = V @ F (V symmetric) ----
        {
            int i = lane, g = warp, j0 = 6 * g;
            float2 a0 = {0.f, 0.f}, a1 = a0, a2 = a0;
            #pragma unroll 8
            for (int s = 0; s < NS; ++s) {
                float v = sV[i * LDV + s];
                float2 f0 = *(const float2*)&Fp[s * LDF + j0];
                float2 f1 = *(const float2*)&Fp[s * LDF + j0 + 2];
                float2 f2 = *(const float2*)&Fp[s * LDF + j0 + 4];
                a0.x += v * f0.x; a0.y += v * f0.y;
                a1.x += v * f1.x; a1.y += v * f1.y;
                a2.x += v * f2.x; a2.y += v * f2.y;
            }
            *(float2*)&sW[i * LDF + j0]     = a0;
            *(float2*)&sW[i * LDF + j0 + 2] = a1;
            *(float2*)&sW[i * LDF + j0 + 4] = a2;
        }
        __syncthreads(); // B1

        // ---- P2: Qm = C + F^T W (192 thr, in-place) ; qv (48 thr) ----
        if (tid < 192) {
            int c4 = tid % 12, r0 = tid / 12;
            float4 q0 = *(const float4*)&sQp[r0 * LDQ + c4 * 4];
            float4 q1 = *(const float4*)&sQp[(r0 + 16) * LDQ + c4 * 4];
            float4 q2 = *(const float4*)&sQp[(r0 + 32) * LDQ + c4 * 4];
            #pragma unroll 8
            for (int s = 0; s < NS; ++s) {
                float4 w = *(const float4*)&sW[s * LDF + c4 * 4];
                float f0 = Fp[s * LDF + r0];
                float f1 = Fp[s * LDF + r0 + 16];
                float f2 = Fp[s * LDF + r0 + 32];
                q0.x += f0 * w.x; q0.y += f0 * w.y; q0.z += f0 * w.z; q0.w += f0 * w.w;
                q1.x += f1 * w.x; q1.y += f1 * w.y; q1.z += f1 * w.z; q1.w += f1 * w.w;
                q2.x += f2 * w.x; q2.y += f2 * w.y; q2.z += f2 * w.z; q2.w += f2 * w.w;
            }
            *(float4*)&sQp[r0 * LDQ + c4 * 4] = q0;
            *(float4*)&sQp[(r0 + 16) * LDQ + c4 * 4] = q1;
            *(float4*)&sQp[(r0 + 32) * LDQ + c4 * 4] = q2;
        } else {
            int j = tid - 192;
            if (j < NN) {
                const float* sv = sm + O_SVV;
                const float* sfv = sm + O_SFV(p);
                float a = sm[O_SCV(p) + j];
                #pragma unroll 8
                for (int s = 0; s < NS; ++s)
                    a += Fp[s * LDF + j] * sv[s] + sW[s * LDF + j] * sfv[s];
                sm[O_SQV + j] = a;
            }
        }
        __syncthreads(); // B2

        if (warp == 0)
            factor_w0(lane, sQp, sm + O_SQV + NS, sm + O_SK, sm + O_SKV);
        __syncthreads(); // B3

        p3_phase(sm, tid, t, b, sQp, sm + O_SQV);
        __syncthreads(); // B4
    }

    // =============================== FORWARD ================================
    if (tid < NS) sm[O_SX + tid] = x0[(size_t)b * NS + tid];
    issue_fwd(sm, tid, 0, b, Fin, fin, 0, true);
    CP_COMMIT();

    for (int t = 0; t < TT - 1; ++t) {
        const int pf = t & 1;
        issue_fwd(sm, tid, t + 1, b, Fin, fin, 1 - pf, t + 1 < TT - 1);
        CP_COMMIT();
        CP_WAIT(1);
        __syncthreads();

        if (warp == 0) {
            const float* sK2 = sm + O_K2(pf);
            int u = lane & 15, h = lane >> 4;
            float acc = 0.0f;
            #pragma unroll
            for (int ii = 0; ii < 16; ++ii)
                acc += sK2[u * LDK + h * 16 + ii] * sm[O_SX + h * 16 + ii];
            acc += __shfl_xor_sync(FULLM, acc, 16);
            if (lane < 16) sm[O_SX + NS + lane] = acc + sm[O_KV2(pf) + lane];
        }
        __syncthreads();

        if (tid < NN) out[((size_t)t * NB + b) * NN + tid] = sm[O_SX + tid];
        if (tid < NS) {
            const float* Fp = sm + O_SF(pf);
            float a = sm[O_SFV(pf) + tid];
            #pragma unroll 8
            for (int j = 0; j < NN; ++j) a += Fp[tid * LDF + j] * sm[O_SX + j];
            sm[O_SX2 + tid] = a;
        }
        __syncthreads();
        if (tid < NS) sm[O_SX + tid] = sm[O_SX2 + tid];
    }

    // final step t = TT-1 (buffer parity 1)
    CP_WAIT(0);
    __syncthreads();
    if (warp == 0) {
        const float* sK2 = sm + O_K2(1);
        int u = lane & 15, h = lane >> 4;
        float acc = 0.0f;
        #pragma unroll
        for (int ii = 0; ii < 16; ++ii)
            acc += sK2[u * LDK + h * 16 + ii] * sm[O_SX + h * 16 + ii];
        acc += __shfl_xor_sync(FULLM, acc, 16);
        if (lane < 16) sm[O_SX + NS + lane] = acc + sm[O_KV2(1) + lane];
    }
    __syncthreads();
    if (tid < NN) out[((size_t)(TT - 1) * NB + b) * NN + tid] = sm[O_SX + tid];
}

extern "C" void kernel_launch(void* const* d_in, const int* in_sizes, int n_in,
                              void* d_out, int out_size) {
    const float *x0 = nullptr, *C = nullptr, *c = nullptr, *F = nullptr, *f = nullptr;
    for (int i = 0; i < n_in; ++i) {
        long long s = in_sizes[i];
        if (s == (long long)TT * NB * NN * NN) C = (const float*)d_in[i];
        else if (s == (long long)TT * NB * NN) c = (const float*)d_in[i];
        else if (s == (long long)(TT - 1) * NB * NS * NN) F = (const float*)d_in[i];
        else if (s == (long long)(TT - 1) * NB * NS) f = (const float*)d_in[i];
        else if (s == (long long)NB * NS) x0 = (const float*)d_in[i];
    }
    float* out = (float*)d_out;
    lqr_kernel<<<NB, NTHREADS>>>(x0, C, c, F, f, out);
}